// round 9
// baseline (speedup 1.0000x reference)
#include <cuda_runtime.h>
#include <math.h>

#define BATCH 2048
#define TSTEPS 1000
#define NI 40
#define NH 16
#define NR 32
#define NO 2

#define CHUNKS 10
#define CHLEN (TSTEPS / CHUNKS)   // 100 steps = 50 pairs per warp
#define NPAIR (CHLEN / 2)         // 50

#define OUT_LOSS 0
#define OUT_D2   1
#define OUT_CORR (1 + (size_t)BATCH * TSTEPS * NO)
#define OUT_TOT  (OUT_CORR + 1)

// 262 MB scratch: pre-scaled dendritic currents pc[b][t][r] = (1-beta_r)*cur
__device__ __align__(16) float g_cur[(size_t)BATCH * TSTEPS * NR];
// 4 MB scratch: packed spike ballots per recur-warp (4 batches) per step
__device__ __align__(16) uint2 g_ball[(size_t)(BATCH / 4) * TSTEPS];

__device__ __forceinline__ void fma2(unsigned long long& acc,
                                     unsigned long long a,
                                     unsigned long long b) {
    asm("fma.rn.f32x2 %0, %1, %2, %3;" : "=l"(acc) : "l"(a), "l"(b), "l"(acc));
}
__device__ __forceinline__ unsigned long long packf2(float lo, float hi) {
    unsigned long long r;
    asm("mov.b64 %0, {%1, %2};" : "=l"(r) : "f"(lo), "f"(hi));
    return r;
}
__device__ __forceinline__ void unpackf2(unsigned long long v, float& lo, float& hi) {
    asm("mov.b64 {%0, %1}, %2;" : "=f"(lo), "=f"(hi) : "l"(v));
}
__device__ __forceinline__ float sigm(float v) { return 1.0f / (1.0f + expf(-v)); }

// ---------------- Kernel A: masked matvec, 2 steps per warp-iter ------------
// warp w: batch b = w/CHUNKS, steps [c*CHLEN, (c+1)*CHLEN).
// lane = half*16 + rl: half selects step parity within a pair,
// rl in [0,16) owns rows 2rl, 2rl+1 over the full k range.
__global__ __launch_bounds__(128) void matvec_kernel(
    const float* __restrict__ x,     // [B, T, NI]
    const float* __restrict__ W1,    // [NR, NI]
    const float* __restrict__ mask,  // [NR, NI]
    const float* __restrict__ tau_n, // [NR]
    float*       __restrict__ out)
{
    if (blockIdx.x == 0 && threadIdx.x == 0) {
        out[OUT_LOSS] = 0.0f;
        int c = 0;
        for (int t = 0; t < TSTEPS; ++t)
            if (t > 10 && ((t - 10) % 15) > 5) c++;
        out[OUT_CORR] = 0.0f;
        out[OUT_TOT] = (float)c * (float)BATCH;
    }

    const int wib  = threadIdx.x >> 5;            // warp in block, 0..3
    const int lane = threadIdx.x & 31;
    const int w    = blockIdx.x * 4 + wib;
    const int b    = w / CHUNKS;
    const int t0   = (w - b * CHUNKS) * CHLEN;

    const int half = lane >> 4;                   // which step of the pair
    const int rl   = lane & 15;
    const int row0 = 2 * rl;
    const int row1 = row0 + 1;

    // 4-slot ring of step-pairs: 320B per slot (2 steps x 160B, contiguous)
    __shared__ __align__(16) float xbuf[4][4][80];

    const float om0 = 1.0f - sigm(tau_n[row0]);
    const float om1 = 1.0f - sigm(tau_n[row1]);

    // full 40-k masked, (1-beta)-scaled weight rows as packed f32x2
    unsigned long long wp0[20], wp1[20];
    #pragma unroll
    for (int j = 0; j < 20; ++j) {
        int k = 2 * j;
        wp0[j] = packf2(W1[row0 * NI + k]     * mask[row0 * NI + k]     * om0,
                        W1[row0 * NI + k + 1] * mask[row0 * NI + k + 1] * om0);
        wp1[j] = packf2(W1[row1 * NI + k]     * mask[row1 * NI + k]     * om1,
                        W1[row1 * NI + k + 1] * mask[row1 * NI + k + 1] * om1);
    }

    const char* xsrc = reinterpret_cast<const char*>(
        x + ((size_t)b * TSTEPS + t0) * NI);
    float* cp = g_cur + ((size_t)b * TSTEPS + t0) * NR;

    // cp.async staging: 20 lanes copy 16B each -> 320B pair
    const bool cpl = lane < 20;
    unsigned sdst[4];
    #pragma unroll
    for (int s = 0; s < 4; ++s)
        sdst[s] = (unsigned)__cvta_generic_to_shared(&xbuf[wib][s][0]) + lane * 16;

    // prologue: issue pairs 0,1,2
    #pragma unroll
    for (int p = 0; p < 3; ++p) {
        if (cpl) {
            const char* src = xsrc + (size_t)p * 320 + lane * 16;
            asm volatile("cp.async.cg.shared.global [%0], [%1], 16;"
                         :: "r"(sdst[p]), "l"(src));
        }
        asm volatile("cp.async.commit_group;");
    }

    for (int i = 0; i < NPAIR; ++i) {
        asm volatile("cp.async.wait_group 2;");
        __syncwarp();

        // dot over full k for this lane's step (10 LDS.128, 2 regions/warp)
        const ulonglong2* xr = reinterpret_cast<const ulonglong2*>(
            &xbuf[wib][i & 3][half * 40]);
        unsigned long long a0 = 0ull, a1 = 0ull, b0 = 0ull, b1 = 0ull;
        #pragma unroll
        for (int j = 0; j < 10; ++j) {
            ulonglong2 v = xr[j];
            fma2(a0, wp0[2 * j],     v.x);
            fma2(a1, wp0[2 * j + 1], v.y);
            fma2(b0, wp1[2 * j],     v.x);
            fma2(b1, wp1[2 * j + 1], v.y);
        }
        float s0, s1, s2, s3, s4, s5, s6, s7;
        unpackf2(a0, s0, s1);
        unpackf2(a1, s2, s3);
        unpackf2(b0, s4, s5);
        unpackf2(b1, s6, s7);
        float h0 = (s0 + s1) + (s2 + s3);
        float h1 = (s4 + s5) + (s6 + s7);

        // both steps of the pair stored by one warp-wide STG.64 (256B)
        *reinterpret_cast<float2*>(cp + (2 * i + half) * NR + row0)
            = make_float2(h0, h1);

        // issue pair i+3 (clamped to last pair; dead slots never read)
        int np = (i + 3 < NPAIR) ? i + 3 : NPAIR - 1;
        if (cpl) {
            const char* src = xsrc + (size_t)np * 320 + lane * 16;
            asm volatile("cp.async.cg.shared.global [%0], [%1], 16;"
                         :: "r"(sdst[(i + 3) & 3]), "l"(src));
        }
        asm volatile("cp.async.commit_group;");
    }
}

// ---------------- Kernel B: pure state recurrence ---------------------------
// lane gl (0..7) of each 8-lane group owns rows 4gl..4gl+3 = neurons 2gl,2gl+1
#define PD 20

__global__ __launch_bounds__(128) void recur_kernel(
    const float* __restrict__ tau_m,  // [NH]
    const float* __restrict__ tau_n)  // [NR]
{
    const int lane = threadIdx.x & 31;
    const int warp = (blockIdx.x * 128 + threadIdx.x) >> 5;
    const int g    = lane >> 3;
    const int gl   = lane & 7;
    const int b    = warp * 4 + g;
    const unsigned FULL = 0xffffffffu;

    const float4 tn4 = *reinterpret_cast<const float4*>(tau_n + gl * 4);
    const float be0 = sigm(tn4.x), be1 = sigm(tn4.y);
    const float be2 = sigm(tn4.z), be3 = sigm(tn4.w);
    const float2 tm2 = *reinterpret_cast<const float2*>(tau_m + gl * 2);
    const float alA = sigm(tm2.x), omA = 1.0f - alA;
    const float alB = sigm(tm2.y), omB = 1.0f - alB;

    const float4* cp = reinterpret_cast<const float4*>(g_cur)
                     + (size_t)b * TSTEPS * (NR / 4) + gl;
    uint2* bp = g_ball + (size_t)warp * TSTEPS;

    float4 pc[PD];
    #pragma unroll
    for (int j = 0; j < PD; ++j) pc[j] = cp[(size_t)j * (NR / 4)];

    float d0 = 0.f, d1 = 0.f, d2 = 0.f, d3 = 0.f;
    float memA = 0.f, memB = 0.f, spkA = 0.f, spkB = 0.f;

    for (int tt = 0; tt < TSTEPS; tt += PD) {
        #pragma unroll
        for (int u = 0; u < PD; ++u) {
            const int t = tt + u;
            float4 v = pc[u];
            const int tn_ = t + PD;
            if (tn_ < TSTEPS) pc[u] = cp[(size_t)tn_ * (NR / 4)];

            d0 = fmaf(be0, d0, v.x);
            d1 = fmaf(be1, d1, v.y);
            d2 = fmaf(be2, d2, v.z);
            d3 = fmaf(be3, d3, v.w);
            float lA = d0 + d1;
            float lB = d2 + d3;

            memA = fmaf(alA, memA - spkA, omA * lA);
            memB = fmaf(alB, memB - spkB, omB * lB);
            bool sA = memA > 1.0f;               // VTH = 1
            bool sB = memB > 1.0f;
            spkA = sA ? 1.0f : 0.0f;
            spkB = sB ? 1.0f : 0.0f;

            unsigned bA = __ballot_sync(FULL, sA);
            unsigned bB = __ballot_sync(FULL, sB);
            if (lane == 0) bp[t] = make_uint2(bA, bB);
        }
    }
}

// ---------------- Kernel C: parallel logits + CE/accuracy -------------------
#define CBLK 256

__global__ __launch_bounds__(CBLK) void logits_kernel(
    const int*   __restrict__ target, // [B, T]
    const float* __restrict__ W2,     // [NO, NH]
    const float* __restrict__ b2,     // [NO]
    float*       __restrict__ out)
{
    __shared__ float LA0[256], LA1[256], LB0[256], LB1[256];
    __shared__ float redL[CBLK / 32], redC[CBLK / 32];

    {
        int m = threadIdx.x;
        if (m < 256) {
            float a0 = 0.f, a1 = 0.f, c0 = 0.f, c1 = 0.f;
            #pragma unroll
            for (int gl = 0; gl < 8; ++gl) {
                if ((m >> gl) & 1) {
                    a0 += W2[2 * gl];
                    a1 += W2[NH + 2 * gl];
                    c0 += W2[2 * gl + 1];
                    c1 += W2[NH + 2 * gl + 1];
                }
            }
            LA0[m] = a0; LA1[m] = a1; LB0[m] = c0; LB1[m] = c1;
        }
    }
    __syncthreads();

    const float b20 = b2[0], b21 = b2[1];
    const int total = BATCH * TSTEPS;
    const int stride = gridDim.x * CBLK;

    float lossAcc = 0.0f;
    int   corrAcc = 0;

    for (int i = blockIdx.x * CBLK + threadIdx.x; i < total; i += stride) {
        int b = i / TSTEPS;
        int t = i - b * TSTEPS;
        uint2 ball = g_ball[(size_t)(b >> 2) * TSTEPS + t];
        int sh = (b & 3) * 8;
        int a = (ball.x >> sh) & 255;
        int c = (ball.y >> sh) & 255;
        float l0 = b20 + LA0[a] + LB0[c];
        float l1 = b21 + LA1[a] + LB1[c];
        out[OUT_D2 + 2 * (size_t)i]     = l0;
        out[OUT_D2 + 2 * (size_t)i + 1] = l1;

        bool flag = (t > 10) && (((t - 10) % 15) > 5);
        if (flag) {
            int tgt = target[i];
            float z  = l1 - l0;
            float p1 = 1.0f / (1.0f + __expf(-z));
            float p0 = 1.0f - p1;
            float lse = __logf(__expf(p0) + __expf(p1));  // double-softmax CE
            float ptgt = tgt ? p1 : p0;
            lossAcc += (lse - ptgt);
            corrAcc += (((z > 0.0f) ? 1 : 0) == tgt);
        }
    }

    const unsigned FULL = 0xffffffffu;
    float corrF = (float)corrAcc;
    #pragma unroll
    for (int o = 16; o > 0; o >>= 1) {
        lossAcc += __shfl_xor_sync(FULL, lossAcc, o);
        corrF   += __shfl_xor_sync(FULL, corrF, o);
    }
    int wid = threadIdx.x >> 5;
    if ((threadIdx.x & 31) == 0) { redL[wid] = lossAcc; redC[wid] = corrF; }
    __syncthreads();
    if (threadIdx.x == 0) {
        float L = 0.f, C = 0.f;
        #pragma unroll
        for (int k = 0; k < CBLK / 32; ++k) { L += redL[k]; C += redC[k]; }
        atomicAdd(&out[OUT_LOSS], L * (1.0f / (float)BATCH));
        atomicAdd(&out[OUT_CORR], C);
    }
}

extern "C" void kernel_launch(void* const* d_in, const int* in_sizes, int n_in,
                              void* d_out, int out_size) {
    const float* x      = (const float*)d_in[0];
    const int*   target = (const int*)  d_in[1];
    const float* W1     = (const float*)d_in[2];
    const float* tau_m  = (const float*)d_in[3];
    const float* tau_n  = (const float*)d_in[4];
    const float* mask   = (const float*)d_in[5];
    const float* W2     = (const float*)d_in[6];
    const float* b2     = (const float*)d_in[7];
    float* out = (float*)d_out;

    matvec_kernel<<<(BATCH * CHUNKS) / 4, 128>>>(x, W1, mask, tau_n, out);
    recur_kernel<<<(BATCH / 4) * 32 / 128, 128>>>(tau_m, tau_n);
    logits_kernel<<<1024, CBLK>>>(target, W2, b2, out);
}